// round 11
// baseline (speedup 1.0000x reference)
#include <cuda_runtime.h>
#include <cuda_fp16.h>
#include <math.h>

#define B_   16
#define H_   128
#define W_   128
#define CIN1 256
#define COUT 128

// Scratch (device globals; no allocation). All half2 stored as unsigned.
__device__ unsigned g_xh [(size_t)B_ * 128 * H_ * W_];  // x pairs / conv3 fp32 out
__device__ unsigned g_uph[(size_t)B_ *  64 * H_ * W_];  // up pairs
__device__ unsigned g_dnh[(size_t)B_ *  64 * H_ * W_];  // down/merge pairs
__device__ unsigned g_whu[16 * 9 * 1024];               // packed A: [chunk][tap][ci2][co]
__device__ unsigned g_whd[16 * 9 * 1024];
__device__ unsigned g_whp[ 8 * 9 * 1024];

// ---------------- helpers ----------------
__device__ __forceinline__ void cpa16(unsigned* dst, const unsigned* src, bool ok) {
    unsigned d = (unsigned)__cvta_generic_to_shared(dst);
    int sz = ok ? 16 : 0;
    asm volatile("cp.async.ca.shared.global [%0], [%1], 16, %2;" :: "r"(d), "l"(src), "r"(sz));
}
#define CPCOMMIT() asm volatile("cp.async.commit_group;")
#define CPWAIT(n)  asm volatile("cp.async.wait_group %0;"::"n"(n))

__device__ __forceinline__ void mma_f16(float* c, const unsigned* a, unsigned b0, unsigned b1) {
    asm volatile(
        "mma.sync.aligned.m16n8k16.row.col.f32.f16.f16.f32 "
        "{%0,%1,%2,%3},{%4,%5,%6,%7},{%8,%9},{%0,%1,%2,%3};"
        : "+f"(c[0]), "+f"(c[1]), "+f"(c[2]), "+f"(c[3])
        : "r"(a[0]), "r"(a[1]), "r"(a[2]), "r"(a[3]), "r"(b0), "r"(b1));
}
__device__ __forceinline__ unsigned h2u(float lo, float hi) {
    __half2 h = __floats2half2_rn(lo, hi);
    return *(unsigned*)&h;
}

// smem words (double buffered): ws[tap][ci2][136]=9792, xs[row][ci2][136] (3 rows)=3264
#define WS_W 9792
#define XS_W 3264
#define BUF_W (WS_W + XS_W)
#define SMEM_BYTES (2 * BUF_W * 4)

// ---------------------------------------------------------------------------
// fp16 mma.sync implicit-GEMM 3x3 conv + BN (+ReLU), cp.async double-buffered.
// Block=256, 2 CTAs/SM. Tile M=128co x 128px (1 output row), K=16ci/chunk.
// Warps: 4 m-warps (32co) x 2 n-warps (64w); warp tile 32x64.
// ---------------------------------------------------------------------------
template <int NCC, bool RELU, bool OUTH>
__global__ __launch_bounds__(256, 2)
void conv_h(const unsigned* __restrict__ xh, const unsigned* __restrict__ wh,
            const float* __restrict__ gam, const float* __restrict__ bet,
            const float* __restrict__ mu,  const float* __restrict__ var,
            unsigned* __restrict__ outv)
{
    extern __shared__ unsigned sm[];
    unsigned* wsb[2] = { sm,        sm + BUF_W        };
    unsigned* xsb[2] = { sm + WS_W, sm + BUF_W + WS_W };

    const int tid  = threadIdx.x;
    const int b    = blockIdx.y;
    const int h0   = blockIdx.x;          // one output row per CTA

    const int warp = tid >> 5;
    const int lane = tid & 31;
    const int g    = lane >> 2;
    const int tig  = lane & 3;

    const int mwarp  = warp & 3;          // 4 m-warps, 32 co each
    const int nwarp  = warp >> 2;         // 2 n-warps, 64 w each
    const int wn0    = nwarp * 64;
    const int cobase = mwarp * 32;

    // static-zero halo cols (3 <- w=-1, 132 <- w=128): 2 bufs x 3 rows x 8 ci2 x 2 cols
    if (tid < 96) {
        int bufsel = tid & 1, colsel = (tid >> 1) & 1;
        int ci2 = (tid >> 2) & 7, row = (tid >> 5) & 3;  // row 0..2 (tid<96)
        xsb[bufsel][row * 1088 + ci2 * 136 + (colsel ? 132 : 3)] = 0u;
    }

    float acc[2][8][4];
#pragma unroll
    for (int mt = 0; mt < 2; mt++)
#pragma unroll
        for (int nt = 0; nt < 8; nt++)
#pragma unroll
            for (int i = 0; i < 4; i++) acc[mt][nt][i] = 0.f;

    auto stage = [&](int c) {
        unsigned* ws = wsb[c & 1];
        unsigned* xs = xsb[c & 1];
        // weights: 9 taps x 8 ci2 x 128 co (2304 x 16B)
#pragma unroll
        for (int k = 0; k < 9; k++) {
            int fi = tid + (k << 8);
            int tap = fi >> 8, rem = fi & 255, ci2 = rem >> 5, cg = rem & 31;
            cpa16(ws + (tap * 8 + ci2) * 136 + cg * 4,
                  wh + (size_t)(c * 9 + tap) * 1024 + ci2 * 128 + cg * 4, true);
        }
        // x: 3 rows x 8 ci2 x 128 half2 (768 x 16B), zero-fill OOB rows
#pragma unroll
        for (int k = 0; k < 3; k++) {
            int fi = tid + (k << 8);
            int row = fi >> 8, rem = fi & 255, ci2 = rem >> 5, wg = rem & 31;
            int gh = h0 - 1 + row;
            bool ok = (gh >= 0) && (gh < H_);
            cpa16(xs + row * 1088 + ci2 * 136 + 4 + wg * 4,
                  xh + ((size_t)((b * NCC + c) * 8 + ci2) * H_ + (ok ? gh : 0)) * W_ + wg * 4,
                  ok);
        }
    };

    stage(0); CPCOMMIT();
    if (NCC > 1) { stage(1); CPCOMMIT(); }

    for (int c = 0; c < NCC; c++) {
        if (c + 1 < NCC) { CPWAIT(1); } else { CPWAIT(0); }
        __syncthreads();

        const unsigned* ws = wsb[c & 1];
        const unsigned* xs = xsb[c & 1];

#pragma unroll
        for (int dh = 0; dh < 3; dh++)
#pragma unroll
            for (int dw = 0; dw < 3; dw++) {
                const int tap = dh * 3 + dw;
                const unsigned* wr0 = ws + (tap * 8 + tig) * 136;
                const unsigned* wr1 = ws + (tap * 8 + tig + 4) * 136;
                unsigned a[2][4];
#pragma unroll
                for (int mt = 0; mt < 2; mt++) {
                    int cb = cobase + mt * 16 + g;
                    a[mt][0] = wr0[cb];
                    a[mt][1] = wr0[cb + 8];
                    a[mt][2] = wr1[cb];
                    a[mt][3] = wr1[cb + 8];
                }
                const unsigned* p0 = xs + dh * 1088 + tig * 136 + wn0 + g + dw + 3;
                const unsigned* p1 = p0 + 4 * 136;
#pragma unroll
                for (int nt = 0; nt < 8; nt++) {
                    unsigned b0 = p0[nt * 8];
                    unsigned b1 = p1[nt * 8];
#pragma unroll
                    for (int mt = 0; mt < 2; mt++)
                        mma_f16(acc[mt][nt], a[mt], b0, b1);
                }
            }
        __syncthreads();   // buffer reuse fence before stage(c+2)
        if (c + 2 < NCC) { stage(c + 2); CPCOMMIT(); }
    }

    // ---- epilogue: BN (+ReLU) ----
    const int h = h0;
#pragma unroll
    for (int mt = 0; mt < 2; mt++) {
        int bi = mwarp * 2 + mt;           // 16-block index 0..7
        int ca = bi * 16 + g;              // pair lo
        int cb2 = ca + 8;                  // pair hi
        float inva = gam[ca]  * rsqrtf(var[ca]  + 1e-5f);
        float bia  = bet[ca]  - mu[ca]  * inva;
        float invb = gam[cb2] * rsqrtf(var[cb2] + 1e-5f);
        float bib  = bet[cb2] - mu[cb2] * invb;
        if (OUTH) {
            int j = bi * 8 + g;            // pair row 0..63
            unsigned* rp = outv + ((size_t)(b * 64 + j) * H_ + h) * W_;
#pragma unroll
            for (int nt = 0; nt < 8; nt++) {
                int w0 = wn0 + nt * 8 + 2 * tig;
                float v0 = acc[mt][nt][0] * inva + bia;
                float v1 = acc[mt][nt][1] * inva + bia;
                float v2 = acc[mt][nt][2] * invb + bib;
                float v3 = acc[mt][nt][3] * invb + bib;
                if (RELU) { v0=fmaxf(v0,0.f); v1=fmaxf(v1,0.f); v2=fmaxf(v2,0.f); v3=fmaxf(v3,0.f); }
                uint2 q; q.x = h2u(v0, v2); q.y = h2u(v1, v3);
                *(uint2*)(rp + w0) = q;
            }
        } else {
            float* rp0 = (float*)outv + ((size_t)(b * COUT + ca)  * H_ + h) * W_;
            float* rp1 = (float*)outv + ((size_t)(b * COUT + cb2) * H_ + h) * W_;
#pragma unroll
            for (int nt = 0; nt < 8; nt++) {
                int w0 = wn0 + nt * 8 + 2 * tig;
                float v0 = acc[mt][nt][0] * inva + bia;
                float v1 = acc[mt][nt][1] * inva + bia;
                float v2 = acc[mt][nt][2] * invb + bib;
                float v3 = acc[mt][nt][3] * invb + bib;
                if (RELU) { v0=fmaxf(v0,0.f); v1=fmaxf(v1,0.f); v2=fmaxf(v2,0.f); v3=fmaxf(v3,0.f); }
                *(float2*)(rp0 + w0) = make_float2(v0, v1);
                *(float2*)(rp1 + w0) = make_float2(v2, v3);
            }
        }
    }
}

// ---------------------------------------------------------------------------
// Prep: x NCHW fp32 -> [b][ci2][h][w] half2 (pair = 2ci2, 2ci2+1).
// ---------------------------------------------------------------------------
__global__ void xpose_h(const float* __restrict__ x, unsigned* __restrict__ xh)
{
    size_t idx = (size_t)blockIdx.x * 256 + threadIdx.x;   // B*128*H*W
    int w = idx & 127;
    int h = (idx >> 7) & 127;
    int ci2 = (idx >> 14) & 127;
    int b = idx >> 21;
    float x0 = x[(((size_t)b * CIN1 + 2 * ci2)     * H_ + h) * W_ + w];
    float x1 = x[(((size_t)b * CIN1 + 2 * ci2 + 1) * H_ + h) * W_ + w];
    xh[idx] = h2u(x0, x1);
}

// Prep: weights [co][ci][3][3] -> [chunk][tap][ci2][co] half2.
// PAIR8: pair j = (16*(j>>3)+(j&7), +8); else (2j, 2j+1).
template <int CIN, bool PAIR8>
__global__ void wpack_h(const float* __restrict__ w, unsigned* __restrict__ wo)
{
    int idx = blockIdx.x * 256 + threadIdx.x;     // (CIN/2)*9*128
    if (idx >= (CIN / 2) * 9 * 128) return;
    int co = idx & 127;
    int tap = (idx >> 7) % 9;
    int jg = idx / (9 * 128);
    int ca, cbb;
    if (PAIR8) { ca = (jg >> 3) * 16 + (jg & 7); cbb = ca + 8; }
    else       { ca = 2 * jg;                    cbb = ca + 1; }
    float wa = w[((size_t)co * CIN + ca)  * 9 + tap];
    float wb = w[((size_t)co * CIN + cbb) * 9 + tap];
    wo[((size_t)((jg >> 3) * 9 + tap)) * 1024 + (jg & 7) * 128 + co] = h2u(wa, wb);
}

// ---------------------------------------------------------------------------
// TopPool (reverse cummax over H) + add on half2 pair tensors.
// ---------------------------------------------------------------------------
__global__ void tpool_h(const unsigned* __restrict__ up, const unsigned* __restrict__ dn,
                        unsigned* __restrict__ mg)
{
    int idx = blockIdx.x * 256 + threadIdx.x;   // B*64*W
    int w = idx & 127;
    int bj = idx >> 7;
    size_t base = (size_t)bj * H_ * W_ + w;
    unsigned ru = 0xFC00FC00u;                  // half2(-inf,-inf)
    __half2 run = *(__half2*)&ru;
#pragma unroll 4
    for (int h = H_ - 1; h >= 0; h--) {
        size_t o = base + (size_t)h * W_;
        __half2 u = *(__half2*)&up[o];
        __half2 d = *(__half2*)&dn[o];
        run = __hmax2(run, u);
        __half2 m = __hadd2(run, d);
        mg[o] = *(unsigned*)&m;
    }
}

// ---------------------------------------------------------------------------
// LeftPool (reverse cummax over W), NCHW fp32, Hillis-Steele per row.
// ---------------------------------------------------------------------------
__global__ void leftpool(const float* __restrict__ in, float* __restrict__ out)
{
    __shared__ float s[W_];
    size_t base = (size_t)blockIdx.x * W_;
    int w = threadIdx.x;
    float v = in[base + w];
    s[w] = v; __syncthreads();
#pragma unroll
    for (int off = 1; off < W_; off <<= 1) {
        float o = (w + off < W_) ? s[w + off] : -INFINITY;
        __syncthreads();
        v = fmaxf(v, o); s[w] = v;
        __syncthreads();
    }
    out[base + w] = v;
}

// ---------------------------------------------------------------------------
extern "C" void kernel_launch(void* const* d_in, const int* in_sizes, int n_in,
                              void* d_out, int out_size)
{
    const float* x      = (const float*)d_in[0];
    const float* w_up   = (const float*)d_in[1];
    const float* up_g   = (const float*)d_in[2];
    const float* up_b   = (const float*)d_in[3];
    const float* up_m   = (const float*)d_in[4];
    const float* up_v   = (const float*)d_in[5];
    const float* w_down = (const float*)d_in[6];
    const float* dn_g   = (const float*)d_in[7];
    const float* dn_b   = (const float*)d_in[8];
    const float* dn_m   = (const float*)d_in[9];
    const float* dn_v   = (const float*)d_in[10];
    const float* w_p    = (const float*)d_in[11];
    const float* p_g    = (const float*)d_in[12];
    const float* p_b    = (const float*)d_in[13];
    const float* p_m    = (const float*)d_in[14];
    const float* p_v    = (const float*)d_in[15];
    float* outp = (float*)d_out;

    unsigned *xh, *uph, *dnh, *whu, *whd, *whp;
    cudaGetSymbolAddress((void**)&xh,  g_xh);
    cudaGetSymbolAddress((void**)&uph, g_uph);
    cudaGetSymbolAddress((void**)&dnh, g_dnh);
    cudaGetSymbolAddress((void**)&whu, g_whu);
    cudaGetSymbolAddress((void**)&whd, g_whd);
    cudaGetSymbolAddress((void**)&whp, g_whp);

    cudaFuncSetAttribute(conv_h<16, true,  true >, cudaFuncAttributeMaxDynamicSharedMemorySize, SMEM_BYTES);
    cudaFuncSetAttribute(conv_h< 8, false, false>, cudaFuncAttributeMaxDynamicSharedMemorySize, SMEM_BYTES);

    // prep
    {
        size_t n = (size_t)B_ * 128 * H_ * W_;
        xpose_h<<<(unsigned)(n / 256), 256>>>(x, xh);
        wpack_h<CIN1, false><<<(128 * 9 * 128 + 255) / 256, 256>>>(w_up,   whu);
        wpack_h<CIN1, false><<<(128 * 9 * 128 + 255) / 256, 256>>>(w_down, whd);
        wpack_h<COUT, true ><<<( 64 * 9 * 128 + 255) / 256, 256>>>(w_p,    whp);
    }

    dim3 cgrid(H_, B_);
    conv_h<16, true,  true ><<<cgrid, 256, SMEM_BYTES>>>(xh,  whu, up_g, up_b, up_m, up_v, uph);
    conv_h<16, true,  true ><<<cgrid, 256, SMEM_BYTES>>>(xh,  whd, dn_g, dn_b, dn_m, dn_v, dnh);
    tpool_h<<<(B_ * 64 * W_) / 256, 256>>>(uph, dnh, dnh);
    conv_h< 8, false, false><<<cgrid, 256, SMEM_BYTES>>>(dnh, whp, p_g, p_b, p_m, p_v, xh);
    leftpool<<<B_ * COUT * H_, W_>>>((const float*)xh, outp);
}

// round 12
// speedup vs baseline: 1.2480x; 1.2480x over previous
#include <cuda_runtime.h>
#include <cuda_fp16.h>
#include <math.h>

#define B_   16
#define H_   128
#define W_   128
#define CIN1 256
#define COUT 128

// Scratch (device globals; no allocation). All half2 stored as unsigned.
__device__ unsigned g_xh [(size_t)B_ * 128 * H_ * W_];  // x pairs / conv3 fp32 out
__device__ unsigned g_uph[(size_t)B_ *  64 * H_ * W_];  // up pairs
__device__ unsigned g_dnh[(size_t)B_ *  64 * H_ * W_];  // down/merge pairs
__device__ unsigned g_whu[16 * 9 * 1024];               // packed A: [chunk][tap][ci2][co]
__device__ unsigned g_whd[16 * 9 * 1024];
__device__ unsigned g_whp[ 8 * 9 * 1024];

// ---------------- helpers ----------------
__device__ __forceinline__ void cpa16(unsigned* dst, const unsigned* src, bool ok) {
    unsigned d = (unsigned)__cvta_generic_to_shared(dst);
    int sz = ok ? 16 : 0;
    asm volatile("cp.async.ca.shared.global [%0], [%1], 16, %2;" :: "r"(d), "l"(src), "r"(sz));
}
#define CPCOMMIT() asm volatile("cp.async.commit_group;")
#define CPWAIT(n)  asm volatile("cp.async.wait_group %0;"::"n"(n))

__device__ __forceinline__ void mma_f16(float* c, const unsigned* a, unsigned b0, unsigned b1) {
    asm volatile(
        "mma.sync.aligned.m16n8k16.row.col.f32.f16.f16.f32 "
        "{%0,%1,%2,%3},{%4,%5,%6,%7},{%8,%9},{%0,%1,%2,%3};"
        : "+f"(c[0]), "+f"(c[1]), "+f"(c[2]), "+f"(c[3])
        : "r"(a[0]), "r"(a[1]), "r"(a[2]), "r"(a[3]), "r"(b0), "r"(b1));
}
__device__ __forceinline__ unsigned h2u(float lo, float hi) {
    __half2 h = __floats2half2_rn(lo, hi);
    return *(unsigned*)&h;
}

// smem words (3-deep ring): ws[tap][ci2][136]=9792, xs[row][ci2][136] (4 rows)=4352
#define WS_W 9792
#define XS_W 4352
#define BUF_W (WS_W + XS_W)
#define SMEM_BYTES (3 * BUF_W * 4)

// ---------------------------------------------------------------------------
// fp16 mma.sync implicit-GEMM 3x3 conv + BN (+ReLU), 3-deep cp.async ring.
// Block=256, tile M=128co x 256px (2 rows x 128w), K streamed 16ci/chunk.
// Warps: 2 m-warps (64co) x 4 n-warps (row, 64w); warp tile 64x64.
// ---------------------------------------------------------------------------
template <int NCC, bool RELU, bool OUTH>
__global__ __launch_bounds__(256, 1)
void conv_h(const unsigned* __restrict__ xh, const unsigned* __restrict__ wh,
            const float* __restrict__ gam, const float* __restrict__ bet,
            const float* __restrict__ mu,  const float* __restrict__ var,
            unsigned* __restrict__ outv)
{
    extern __shared__ unsigned sm[];

    const int tid  = threadIdx.x;
    const int b    = blockIdx.y;
    const int h0   = blockIdx.x * 2;

    const int warp = tid >> 5;
    const int lane = tid & 31;
    const int g    = lane >> 2;
    const int tig  = lane & 3;

    const int mwarp  = warp & 1;
    const int nwarp  = warp >> 1;
    const int rloc   = nwarp >> 1;
    const int wn0    = (nwarp & 1) * 64;
    const int cobase = mwarp * 64;

    // static-zero halo cols (3 <- w=-1, 132 <- w=128): 3 bufs x 4 rows x 8 ci2 x 2 cols
    if (tid < 192) {
        int buf = tid >> 6, rem = tid & 63;
        int colsel = rem & 1, ci2 = (rem >> 1) & 7, row = (rem >> 4) & 3;
        sm[buf * BUF_W + WS_W + row * 1088 + ci2 * 136 + (colsel ? 132 : 3)] = 0u;
    }

    float acc[4][8][4];
#pragma unroll
    for (int mt = 0; mt < 4; mt++)
#pragma unroll
        for (int nt = 0; nt < 8; nt++)
#pragma unroll
            for (int i = 0; i < 4; i++) acc[mt][nt][i] = 0.f;

    auto stage = [&](int c) {
        unsigned* ws = sm + (c % 3) * BUF_W;
        unsigned* xs = ws + WS_W;
        // weights: 9 taps x 8 ci2 x 128 co (2304 x 16B)
#pragma unroll
        for (int k = 0; k < 9; k++) {
            int fi = tid + (k << 8);
            int tap = fi >> 8, rem = fi & 255, ci2 = rem >> 5, cg = rem & 31;
            cpa16(ws + (tap * 8 + ci2) * 136 + cg * 4,
                  wh + (size_t)(c * 9 + tap) * 1024 + ci2 * 128 + cg * 4, true);
        }
        // x: 4 rows x 8 ci2 x 128 half2 (1024 x 16B), zero-fill OOB rows
#pragma unroll
        for (int k = 0; k < 4; k++) {
            int fi = tid + (k << 8);
            int row = fi >> 8, rem = fi & 255, ci2 = rem >> 5, wg = rem & 31;
            int gh = h0 - 1 + row;
            bool ok = (gh >= 0) && (gh < H_);
            cpa16(xs + row * 1088 + ci2 * 136 + 4 + wg * 4,
                  xh + ((size_t)((b * NCC + c) * 8 + ci2) * H_ + (ok ? gh : 0)) * W_ + wg * 4,
                  ok);
        }
    };

    stage(0); CPCOMMIT();
    stage(1); CPCOMMIT();

    for (int c = 0; c < NCC; c++) {
        if (c + 1 < NCC) { CPWAIT(1); } else { CPWAIT(0); }
        __syncthreads();   // stage(c) data visible; all warps done with compute(c-1)
        if (c + 2 < NCC) { stage(c + 2); CPCOMMIT(); }   // buf (c+2)%3 == (c-1)%3, free

        const unsigned* ws = sm + (c % 3) * BUF_W;
        const unsigned* xs = ws + WS_W;

#pragma unroll
        for (int dh = 0; dh < 3; dh++)
#pragma unroll
            for (int dw = 0; dw < 3; dw++) {
                const int tap = dh * 3 + dw;
                const unsigned* wr0 = ws + (tap * 8 + tig) * 136;
                const unsigned* wr1 = ws + (tap * 8 + tig + 4) * 136;
                unsigned a[4][4];
#pragma unroll
                for (int mt = 0; mt < 4; mt++) {
                    int cb = cobase + mt * 16 + g;
                    a[mt][0] = wr0[cb];
                    a[mt][1] = wr0[cb + 8];
                    a[mt][2] = wr1[cb];
                    a[mt][3] = wr1[cb + 8];
                }
                const unsigned* p0 = xs + (rloc + dh) * 1088 + tig * 136 + wn0 + g + dw + 3;
                const unsigned* p1 = p0 + 4 * 136;
#pragma unroll
                for (int nt = 0; nt < 8; nt++) {
                    unsigned b0 = p0[nt * 8];
                    unsigned b1 = p1[nt * 8];
#pragma unroll
                    for (int mt = 0; mt < 4; mt++)
                        mma_f16(acc[mt][nt], a[mt], b0, b1);
                }
            }
    }

    // ---- epilogue: BN (+ReLU) ----
    const int h = h0 + rloc;
#pragma unroll
    for (int mt = 0; mt < 4; mt++) {
        int ca = cobase + mt * 16 + g;     // pair lo
        int cb2 = ca + 8;                  // pair hi
        float inva = gam[ca]  * rsqrtf(var[ca]  + 1e-5f);
        float bia  = bet[ca]  - mu[ca]  * inva;
        float invb = gam[cb2] * rsqrtf(var[cb2] + 1e-5f);
        float bib  = bet[cb2] - mu[cb2] * invb;
        if (OUTH) {
            int j = (mwarp * 4 + mt) * 8 + g;   // pair row
            unsigned* rp = outv + ((size_t)(b * 64 + j) * H_ + h) * W_;
#pragma unroll
            for (int nt = 0; nt < 8; nt++) {
                int w0 = wn0 + nt * 8 + 2 * tig;
                float v0 = acc[mt][nt][0] * inva + bia;
                float v1 = acc[mt][nt][1] * inva + bia;
                float v2 = acc[mt][nt][2] * invb + bib;
                float v3 = acc[mt][nt][3] * invb + bib;
                if (RELU) { v0=fmaxf(v0,0.f); v1=fmaxf(v1,0.f); v2=fmaxf(v2,0.f); v3=fmaxf(v3,0.f); }
                uint2 q; q.x = h2u(v0, v2); q.y = h2u(v1, v3);
                *(uint2*)(rp + w0) = q;
            }
        } else {
            float* rp0 = (float*)outv + ((size_t)(b * COUT + ca)  * H_ + h) * W_;
            float* rp1 = (float*)outv + ((size_t)(b * COUT + cb2) * H_ + h) * W_;
#pragma unroll
            for (int nt = 0; nt < 8; nt++) {
                int w0 = wn0 + nt * 8 + 2 * tig;
                float v0 = acc[mt][nt][0] * inva + bia;
                float v1 = acc[mt][nt][1] * inva + bia;
                float v2 = acc[mt][nt][2] * invb + bib;
                float v3 = acc[mt][nt][3] * invb + bib;
                if (RELU) { v0=fmaxf(v0,0.f); v1=fmaxf(v1,0.f); v2=fmaxf(v2,0.f); v3=fmaxf(v3,0.f); }
                *(float2*)(rp0 + w0) = make_float2(v0, v1);
                *(float2*)(rp1 + w0) = make_float2(v2, v3);
            }
        }
    }
}

// ---------------------------------------------------------------------------
// Prep: x NCHW fp32 -> [b][ci2][h][w] half2 (pair = 2ci2, 2ci2+1).
// ---------------------------------------------------------------------------
__global__ void xpose_h(const float* __restrict__ x, unsigned* __restrict__ xh)
{
    size_t idx = (size_t)blockIdx.x * 256 + threadIdx.x;   // B*128*H*W
    int w = idx & 127;
    int h = (idx >> 7) & 127;
    int ci2 = (idx >> 14) & 127;
    int b = idx >> 21;
    float x0 = x[(((size_t)b * CIN1 + 2 * ci2)     * H_ + h) * W_ + w];
    float x1 = x[(((size_t)b * CIN1 + 2 * ci2 + 1) * H_ + h) * W_ + w];
    xh[idx] = h2u(x0, x1);
}

// Prep: weights [co][ci][3][3] -> [chunk][tap][ci2][co] half2.
// PAIR8: pair j = (16*(j>>3)+(j&7), +8); else (2j, 2j+1).
template <int CIN, bool PAIR8>
__global__ void wpack_h(const float* __restrict__ w, unsigned* __restrict__ wo)
{
    int idx = blockIdx.x * 256 + threadIdx.x;     // (CIN/2)*9*128
    if (idx >= (CIN / 2) * 9 * 128) return;
    int co = idx & 127;
    int tap = (idx >> 7) % 9;
    int jg = idx / (9 * 128);
    int ca, cbb;
    if (PAIR8) { ca = (jg >> 3) * 16 + (jg & 7); cbb = ca + 8; }
    else       { ca = 2 * jg;                    cbb = ca + 1; }
    float wa = w[((size_t)co * CIN + ca)  * 9 + tap];
    float wb = w[((size_t)co * CIN + cbb) * 9 + tap];
    wo[((size_t)((jg >> 3) * 9 + tap)) * 1024 + (jg & 7) * 128 + co] = h2u(wa, wb);
}

// ---------------------------------------------------------------------------
// TopPool (reverse cummax over H) + add on half2 pair tensors.
// ---------------------------------------------------------------------------
__global__ void tpool_h(const unsigned* __restrict__ up, const unsigned* __restrict__ dn,
                        unsigned* __restrict__ mg)
{
    int idx = blockIdx.x * 256 + threadIdx.x;   // B*64*W
    int w = idx & 127;
    int bj = idx >> 7;
    size_t base = (size_t)bj * H_ * W_ + w;
    unsigned ru = 0xFC00FC00u;                  // half2(-inf,-inf)
    __half2 run = *(__half2*)&ru;
#pragma unroll 4
    for (int h = H_ - 1; h >= 0; h--) {
        size_t o = base + (size_t)h * W_;
        __half2 u = *(__half2*)&up[o];
        __half2 d = *(__half2*)&dn[o];
        run = __hmax2(run, u);
        __half2 m = __hadd2(run, d);
        mg[o] = *(unsigned*)&m;
    }
}

// ---------------------------------------------------------------------------
// LeftPool (reverse cummax over W), NCHW fp32, Hillis-Steele per row.
// ---------------------------------------------------------------------------
__global__ void leftpool(const float* __restrict__ in, float* __restrict__ out)
{
    __shared__ float s[W_];
    size_t base = (size_t)blockIdx.x * W_;
    int w = threadIdx.x;
    float v = in[base + w];
    s[w] = v; __syncthreads();
#pragma unroll
    for (int off = 1; off < W_; off <<= 1) {
        float o = (w + off < W_) ? s[w + off] : -INFINITY;
        __syncthreads();
        v = fmaxf(v, o); s[w] = v;
        __syncthreads();
    }
    out[base + w] = v;
}

// ---------------------------------------------------------------------------
extern "C" void kernel_launch(void* const* d_in, const int* in_sizes, int n_in,
                              void* d_out, int out_size)
{
    const float* x      = (const float*)d_in[0];
    const float* w_up   = (const float*)d_in[1];
    const float* up_g   = (const float*)d_in[2];
    const float* up_b   = (const float*)d_in[3];
    const float* up_m   = (const float*)d_in[4];
    const float* up_v   = (const float*)d_in[5];
    const float* w_down = (const float*)d_in[6];
    const float* dn_g   = (const float*)d_in[7];
    const float* dn_b   = (const float*)d_in[8];
    const float* dn_m   = (const float*)d_in[9];
    const float* dn_v   = (const float*)d_in[10];
    const float* w_p    = (const float*)d_in[11];
    const float* p_g    = (const float*)d_in[12];
    const float* p_b    = (const float*)d_in[13];
    const float* p_m    = (const float*)d_in[14];
    const float* p_v    = (const float*)d_in[15];
    float* outp = (float*)d_out;

    unsigned *xh, *uph, *dnh, *whu, *whd, *whp;
    cudaGetSymbolAddress((void**)&xh,  g_xh);
    cudaGetSymbolAddress((void**)&uph, g_uph);
    cudaGetSymbolAddress((void**)&dnh, g_dnh);
    cudaGetSymbolAddress((void**)&whu, g_whu);
    cudaGetSymbolAddress((void**)&whd, g_whd);
    cudaGetSymbolAddress((void**)&whp, g_whp);

    cudaFuncSetAttribute(conv_h<16, true,  true >, cudaFuncAttributeMaxDynamicSharedMemorySize, SMEM_BYTES);
    cudaFuncSetAttribute(conv_h< 8, false, false>, cudaFuncAttributeMaxDynamicSharedMemorySize, SMEM_BYTES);

    // prep
    {
        size_t n = (size_t)B_ * 128 * H_ * W_;
        xpose_h<<<(unsigned)(n / 256), 256>>>(x, xh);
        wpack_h<CIN1, false><<<(128 * 9 * 128 + 255) / 256, 256>>>(w_up,   whu);
        wpack_h<CIN1, false><<<(128 * 9 * 128 + 255) / 256, 256>>>(w_down, whd);
        wpack_h<COUT, true ><<<( 64 * 9 * 128 + 255) / 256, 256>>>(w_p,    whp);
    }

    dim3 cgrid(H_ / 2, B_);
    conv_h<16, true,  true ><<<cgrid, 256, SMEM_BYTES>>>(xh,  whu, up_g, up_b, up_m, up_v, uph);
    conv_h<16, true,  true ><<<cgrid, 256, SMEM_BYTES>>>(xh,  whd, dn_g, dn_b, dn_m, dn_v, dnh);
    tpool_h<<<(B_ * 64 * W_) / 256, 256>>>(uph, dnh, dnh);
    conv_h< 8, false, false><<<cgrid, 256, SMEM_BYTES>>>(dnh, whp, p_g, p_b, p_m, p_v, xh);
    leftpool<<<B_ * COUT * H_, W_>>>((const float*)xh, outp);
}

// round 13
// speedup vs baseline: 1.3839x; 1.1089x over previous
#include <cuda_runtime.h>
#include <cuda_fp16.h>
#include <math.h>

#define B_   16
#define H_   128
#define W_   128
#define CIN1 256
#define COUT 128

// Scratch (device globals; no allocation). All half2 stored as unsigned.
__device__ unsigned g_xh [(size_t)B_ * 128 * H_ * W_];  // x pairs
__device__ unsigned g_uph[(size_t)B_ *  64 * H_ * W_];  // up pairs
__device__ unsigned g_dnh[(size_t)B_ *  64 * H_ * W_];  // down/merge pairs
__device__ unsigned g_whu[16 * 9 * 1024];               // packed A: [chunk][tap][ci2][co]
__device__ unsigned g_whd[16 * 9 * 1024];
__device__ unsigned g_whp[ 8 * 9 * 1024];

struct BNP { const float *g, *b, *m, *v; };

// ---------------- helpers ----------------
__device__ __forceinline__ void cpa16(unsigned* dst, const unsigned* src, bool ok) {
    unsigned d = (unsigned)__cvta_generic_to_shared(dst);
    int sz = ok ? 16 : 0;
    asm volatile("cp.async.ca.shared.global [%0], [%1], 16, %2;" :: "r"(d), "l"(src), "r"(sz));
}
#define CPCOMMIT() asm volatile("cp.async.commit_group;")
#define CPWAIT(n)  asm volatile("cp.async.wait_group %0;"::"n"(n))

__device__ __forceinline__ void mma_f16(float* c, const unsigned* a, unsigned b0, unsigned b1) {
    asm volatile(
        "mma.sync.aligned.m16n8k16.row.col.f32.f16.f16.f32 "
        "{%0,%1,%2,%3},{%4,%5,%6,%7},{%8,%9},{%0,%1,%2,%3};"
        : "+f"(c[0]), "+f"(c[1]), "+f"(c[2]), "+f"(c[3])
        : "r"(a[0]), "r"(a[1]), "r"(a[2]), "r"(a[3]), "r"(b0), "r"(b1));
}
__device__ __forceinline__ unsigned h2u(float lo, float hi) {
    __half2 h = __floats2half2_rn(lo, hi);
    return *(unsigned*)&h;
}

// smem words (3-deep ring): ws[tap][ci2][136]=9792, xs[row][ci2][136] (4 rows)=4352
#define WS_W 9792
#define XS_W 4352
#define BUF_W (WS_W + XS_W)
#define SMEM_BYTES (3 * BUF_W * 4)
// scan buffer (conv3 epilogue): 256 rows x pitch 132 fp32 = 135168 B <= SMEM_BYTES

// ---------------------------------------------------------------------------
// fp16 mma.sync implicit-GEMM 3x3 conv + BN (+ReLU), 3-deep cp.async ring.
// Block=256, tile M=128co x 256px (2 rows x 128w), K streamed 16ci/chunk.
// OUT=0: emit half2 pair tensor. OUT=1: fused reverse-cummax over W (LeftPool),
//        emit fp32 NCHW directly.
// gridDim.z=2 selects (w0,p0,o0) vs (w1,p1,o1) per block (merged conv1+conv2).
// ---------------------------------------------------------------------------
template <int NCC, bool RELU, int OUT>
__global__ __launch_bounds__(256, 1)
void conv_h(const unsigned* __restrict__ xh,
            const unsigned* __restrict__ w0p, const unsigned* __restrict__ w1p,
            BNP p0, BNP p1,
            unsigned* __restrict__ o0, unsigned* __restrict__ o1)
{
    extern __shared__ unsigned sm[];

    const int tid  = threadIdx.x;
    const int b    = blockIdx.y;
    const int h0   = blockIdx.x * 2;
    const int z    = blockIdx.z;

    const unsigned* wh = z ? w1p : w0p;
    const BNP       pp = z ? p1 : p0;
    unsigned*     outv = z ? o1 : o0;

    const int warp = tid >> 5;
    const int lane = tid & 31;
    const int g    = lane >> 2;
    const int tig  = lane & 3;

    const int mwarp  = warp & 1;
    const int nwarp  = warp >> 1;
    const int rloc   = nwarp >> 1;
    const int wn0    = (nwarp & 1) * 64;
    const int cobase = mwarp * 64;

    // static-zero halo cols (3 <- w=-1, 132 <- w=128): 3 bufs x 4 rows x 8 ci2 x 2 cols
    if (tid < 192) {
        int buf = tid >> 6, rem = tid & 63;
        int colsel = rem & 1, ci2 = (rem >> 1) & 7, row = (rem >> 4) & 3;
        sm[buf * BUF_W + WS_W + row * 1088 + ci2 * 136 + (colsel ? 132 : 3)] = 0u;
    }

    float acc[4][8][4];
#pragma unroll
    for (int mt = 0; mt < 4; mt++)
#pragma unroll
        for (int nt = 0; nt < 8; nt++)
#pragma unroll
            for (int i = 0; i < 4; i++) acc[mt][nt][i] = 0.f;

    auto stage = [&](int c) {
        unsigned* ws = sm + (c % 3) * BUF_W;
        unsigned* xs = ws + WS_W;
#pragma unroll
        for (int k = 0; k < 9; k++) {
            int fi = tid + (k << 8);
            int tap = fi >> 8, rem = fi & 255, ci2 = rem >> 5, cg = rem & 31;
            cpa16(ws + (tap * 8 + ci2) * 136 + cg * 4,
                  wh + (size_t)(c * 9 + tap) * 1024 + ci2 * 128 + cg * 4, true);
        }
#pragma unroll
        for (int k = 0; k < 4; k++) {
            int fi = tid + (k << 8);
            int row = fi >> 8, rem = fi & 255, ci2 = rem >> 5, wg = rem & 31;
            int gh = h0 - 1 + row;
            bool ok = (gh >= 0) && (gh < H_);
            cpa16(xs + row * 1088 + ci2 * 136 + 4 + wg * 4,
                  xh + ((size_t)((b * NCC + c) * 8 + ci2) * H_ + (ok ? gh : 0)) * W_ + wg * 4,
                  ok);
        }
    };

    stage(0); CPCOMMIT();
    stage(1); CPCOMMIT();

    for (int c = 0; c < NCC; c++) {
        if (c + 1 < NCC) { CPWAIT(1); } else { CPWAIT(0); }
        __syncthreads();   // stage(c) visible; all warps done with compute(c-1)
        if (c + 2 < NCC) { stage(c + 2); CPCOMMIT(); }   // buf (c+2)%3 == (c-1)%3, free

        const unsigned* ws = sm + (c % 3) * BUF_W;
        const unsigned* xs = ws + WS_W;

#pragma unroll
        for (int dh = 0; dh < 3; dh++)
#pragma unroll
            for (int dw = 0; dw < 3; dw++) {
                const int tap = dh * 3 + dw;
                const unsigned* wr0 = ws + (tap * 8 + tig) * 136;
                const unsigned* wr1 = ws + (tap * 8 + tig + 4) * 136;
                unsigned a[4][4];
#pragma unroll
                for (int mt = 0; mt < 4; mt++) {
                    int cb = cobase + mt * 16 + g;
                    a[mt][0] = wr0[cb];
                    a[mt][1] = wr0[cb + 8];
                    a[mt][2] = wr1[cb];
                    a[mt][3] = wr1[cb + 8];
                }
                const unsigned* p0 = xs + (rloc + dh) * 1088 + tig * 136 + wn0 + g + dw + 3;
                const unsigned* p1 = p0 + 4 * 136;
#pragma unroll
                for (int nt = 0; nt < 8; nt++) {
                    unsigned b0 = p0[nt * 8];
                    unsigned b1 = p1[nt * 8];
#pragma unroll
                    for (int mt = 0; mt < 4; mt++)
                        mma_f16(acc[mt][nt], a[mt], b0, b1);
                }
            }
    }

    // ---- epilogue: BN (+ReLU) ----
    const int h = h0 + rloc;
    if (OUT == 0) {
#pragma unroll
        for (int mt = 0; mt < 4; mt++) {
            int ca = cobase + mt * 16 + g;
            int cb2 = ca + 8;
            float inva = pp.g[ca]  * rsqrtf(pp.v[ca]  + 1e-5f);
            float bia  = pp.b[ca]  - pp.m[ca]  * inva;
            float invb = pp.g[cb2] * rsqrtf(pp.v[cb2] + 1e-5f);
            float bib  = pp.b[cb2] - pp.m[cb2] * invb;
            int j = (mwarp * 4 + mt) * 8 + g;   // pair row
            unsigned* rp = outv + ((size_t)(b * 64 + j) * H_ + h) * W_;
#pragma unroll
            for (int nt = 0; nt < 8; nt++) {
                int w0 = wn0 + nt * 8 + 2 * tig;
                float v0 = acc[mt][nt][0] * inva + bia;
                float v1 = acc[mt][nt][1] * inva + bia;
                float v2 = acc[mt][nt][2] * invb + bib;
                float v3 = acc[mt][nt][3] * invb + bib;
                if (RELU) { v0=fmaxf(v0,0.f); v1=fmaxf(v1,0.f); v2=fmaxf(v2,0.f); v3=fmaxf(v3,0.f); }
                uint2 q; q.x = h2u(v0, v2); q.y = h2u(v1, v3);
                *(uint2*)(rp + w0) = q;
            }
        }
    } else {
        // ---- fused LeftPool: BN -> smem -> reverse cummax over W -> fp32 NCHW ----
        float* sc = (float*)sm;               // [256 rows (co*2+r)][pitch 132]
        __syncthreads();                      // mainloop smem reads complete everywhere
#pragma unroll
        for (int mt = 0; mt < 4; mt++) {
            int ca = cobase + mt * 16 + g;
            int cb2 = ca + 8;
            float inva = pp.g[ca]  * rsqrtf(pp.v[ca]  + 1e-5f);
            float bia  = pp.b[ca]  - pp.m[ca]  * inva;
            float invb = pp.g[cb2] * rsqrtf(pp.v[cb2] + 1e-5f);
            float bib  = pp.b[cb2] - pp.m[cb2] * invb;
            float* r0 = sc + (ca * 2 + rloc) * 132;
            float* r1 = sc + (cb2 * 2 + rloc) * 132;
#pragma unroll
            for (int nt = 0; nt < 8; nt++) {
                int w0 = wn0 + nt * 8 + 2 * tig;
                *(float2*)(r0 + w0) = make_float2(acc[mt][nt][0] * inva + bia,
                                                  acc[mt][nt][1] * inva + bia);
                *(float2*)(r1 + w0) = make_float2(acc[mt][nt][2] * invb + bib,
                                                  acc[mt][nt][3] * invb + bib);
            }
        }
        __syncthreads();
        // per-thread serial reverse max-scan of one (co,r) row
        {
            float* rw = sc + tid * 132;
            float run = -INFINITY;
#pragma unroll 4
            for (int w = W_ - 1; w >= 0; w--) {
                run = fmaxf(run, rw[w]);
                rw[w] = run;
            }
        }
        __syncthreads();
        // coalesced float4 store to fp32 NCHW output
        float* outf = (float*)outv;
#pragma unroll
        for (int k = 0; k < 32; k++) {
            int idx4 = tid + (k << 8);        // 8192 float4s
            int co = idx4 >> 6;
            int r  = (idx4 >> 5) & 1;
            int w4 = idx4 & 31;
            float4 q = *(float4*)(sc + (co * 2 + r) * 132 + w4 * 4);
            ((float4*)(outf + (((size_t)b * COUT + co) * H_ + h0 + r) * W_))[w4] = q;
        }
    }
}

// ---------------------------------------------------------------------------
// Prep: x NCHW fp32 -> [b][ci2][h][w] half2 (pair = 2ci2, 2ci2+1).
// ---------------------------------------------------------------------------
__global__ void xpose_h(const float* __restrict__ x, unsigned* __restrict__ xh)
{
    size_t idx = (size_t)blockIdx.x * 256 + threadIdx.x;   // B*128*H*W
    int w = idx & 127;
    int h = (idx >> 7) & 127;
    int ci2 = (idx >> 14) & 127;
    int b = idx >> 21;
    float x0 = x[(((size_t)b * CIN1 + 2 * ci2)     * H_ + h) * W_ + w];
    float x1 = x[(((size_t)b * CIN1 + 2 * ci2 + 1) * H_ + h) * W_ + w];
    xh[idx] = h2u(x0, x1);
}

// Prep: weights [co][ci][3][3] -> [chunk][tap][ci2][co] half2.
// PAIR8: pair j = (16*(j>>3)+(j&7), +8); else (2j, 2j+1).
template <int CIN, bool PAIR8>
__global__ void wpack_h(const float* __restrict__ w, unsigned* __restrict__ wo)
{
    int idx = blockIdx.x * 256 + threadIdx.x;     // (CIN/2)*9*128
    if (idx >= (CIN / 2) * 9 * 128) return;
    int co = idx & 127;
    int tap = (idx >> 7) % 9;
    int jg = idx / (9 * 128);
    int ca, cbb;
    if (PAIR8) { ca = (jg >> 3) * 16 + (jg & 7); cbb = ca + 8; }
    else       { ca = 2 * jg;                    cbb = ca + 1; }
    float wa = w[((size_t)co * CIN + ca)  * 9 + tap];
    float wb = w[((size_t)co * CIN + cbb) * 9 + tap];
    wo[((size_t)((jg >> 3) * 9 + tap)) * 1024 + (jg & 7) * 128 + co] = h2u(wa, wb);
}

// ---------------------------------------------------------------------------
// TopPool (reverse cummax over H) + add on half2 pair tensors.
// ---------------------------------------------------------------------------
__global__ void tpool_h(const unsigned* __restrict__ up, const unsigned* __restrict__ dn,
                        unsigned* __restrict__ mg)
{
    int idx = blockIdx.x * 256 + threadIdx.x;   // B*64*W
    int w = idx & 127;
    int bj = idx >> 7;
    size_t base = (size_t)bj * H_ * W_ + w;
    unsigned ru = 0xFC00FC00u;                  // half2(-inf,-inf)
    __half2 run = *(__half2*)&ru;
#pragma unroll 4
    for (int h = H_ - 1; h >= 0; h--) {
        size_t o = base + (size_t)h * W_;
        __half2 u = *(__half2*)&up[o];
        __half2 d = *(__half2*)&dn[o];
        run = __hmax2(run, u);
        __half2 m = __hadd2(run, d);
        mg[o] = *(unsigned*)&m;
    }
}

// ---------------------------------------------------------------------------
extern "C" void kernel_launch(void* const* d_in, const int* in_sizes, int n_in,
                              void* d_out, int out_size)
{
    const float* x      = (const float*)d_in[0];
    const float* w_up   = (const float*)d_in[1];
    const float* up_g   = (const float*)d_in[2];
    const float* up_b   = (const float*)d_in[3];
    const float* up_m   = (const float*)d_in[4];
    const float* up_v   = (const float*)d_in[5];
    const float* w_down = (const float*)d_in[6];
    const float* dn_g   = (const float*)d_in[7];
    const float* dn_b   = (const float*)d_in[8];
    const float* dn_m   = (const float*)d_in[9];
    const float* dn_v   = (const float*)d_in[10];
    const float* w_p    = (const float*)d_in[11];
    const float* p_g    = (const float*)d_in[12];
    const float* p_b    = (const float*)d_in[13];
    const float* p_m    = (const float*)d_in[14];
    const float* p_v    = (const float*)d_in[15];
    float* outp = (float*)d_out;

    unsigned *xh, *uph, *dnh, *whu, *whd, *whp;
    cudaGetSymbolAddress((void**)&xh,  g_xh);
    cudaGetSymbolAddress((void**)&uph, g_uph);
    cudaGetSymbolAddress((void**)&dnh, g_dnh);
    cudaGetSymbolAddress((void**)&whu, g_whu);
    cudaGetSymbolAddress((void**)&whd, g_whd);
    cudaGetSymbolAddress((void**)&whp, g_whp);

    cudaFuncSetAttribute(conv_h<16, true,  0>, cudaFuncAttributeMaxDynamicSharedMemorySize, SMEM_BYTES);
    cudaFuncSetAttribute(conv_h< 8, false, 1>, cudaFuncAttributeMaxDynamicSharedMemorySize, SMEM_BYTES);

    // prep
    {
        size_t n = (size_t)B_ * 128 * H_ * W_;
        xpose_h<<<(unsigned)(n / 256), 256>>>(x, xh);
        wpack_h<CIN1, false><<<(128 * 9 * 128 + 255) / 256, 256>>>(w_up,   whu);
        wpack_h<CIN1, false><<<(128 * 9 * 128 + 255) / 256, 256>>>(w_down, whd);
        wpack_h<COUT, true ><<<( 64 * 9 * 128 + 255) / 256, 256>>>(w_p,    whp);
    }

    BNP pup = { up_g, up_b, up_m, up_v };
    BNP pdn = { dn_g, dn_b, dn_m, dn_v };
    BNP ppp = { p_g,  p_b,  p_m,  p_v  };

    // conv1 + conv2 merged (z selects weight/BN/output set)
    dim3 g12(H_ / 2, B_, 2);
    conv_h<16, true, 0><<<g12, 256, SMEM_BYTES>>>(xh, whu, whd, pup, pdn, uph, dnh);
    // merge = toppool(up) + down
    tpool_h<<<(B_ * 64 * W_) / 256, 256>>>(uph, dnh, dnh);
    // conv3 + BN + fused LeftPool -> fp32 output
    dim3 g3(H_ / 2, B_, 1);
    conv_h<8, false, 1><<<g3, 256, SMEM_BYTES>>>(dnh, whp, whp, ppp, ppp,
                                                 (unsigned*)outp, (unsigned*)outp);
}

// round 14
// speedup vs baseline: 1.4359x; 1.0376x over previous
#include <cuda_runtime.h>
#include <cuda_fp16.h>
#include <math.h>

#define B_   16
#define H_   128
#define W_   128
#define CIN1 256
#define COUT 128

// Scratch (device globals; no allocation). All half2 stored as unsigned.
__device__ unsigned g_xh [(size_t)B_ * 128 * H_ * W_];  // x pairs
__device__ unsigned g_uph[(size_t)B_ *  64 * H_ * W_];  // up pairs
__device__ unsigned g_dnh[(size_t)B_ *  64 * H_ * W_];  // down/merge pairs
__device__ unsigned g_whu[16 * 9 * 1024];               // packed A: [chunk][tap][ci2][co]
__device__ unsigned g_whd[16 * 9 * 1024];
__device__ unsigned g_whp[ 8 * 9 * 1024];

struct BNP { const float *g, *b, *m, *v; };

// ---------------- helpers ----------------
__device__ __forceinline__ void cpa16(unsigned* dst, const unsigned* src, bool ok) {
    unsigned d = (unsigned)__cvta_generic_to_shared(dst);
    int sz = ok ? 16 : 0;
    asm volatile("cp.async.ca.shared.global [%0], [%1], 16, %2;" :: "r"(d), "l"(src), "r"(sz));
}
#define CPCOMMIT() asm volatile("cp.async.commit_group;")
#define CPWAIT(n)  asm volatile("cp.async.wait_group %0;"::"n"(n))

__device__ __forceinline__ void mma_f16(float* c, const unsigned* a, unsigned b0, unsigned b1) {
    asm volatile(
        "mma.sync.aligned.m16n8k16.row.col.f32.f16.f16.f32 "
        "{%0,%1,%2,%3},{%4,%5,%6,%7},{%8,%9},{%0,%1,%2,%3};"
        : "+f"(c[0]), "+f"(c[1]), "+f"(c[2]), "+f"(c[3])
        : "r"(a[0]), "r"(a[1]), "r"(a[2]), "r"(a[3]), "r"(b0), "r"(b1));
}
__device__ __forceinline__ unsigned h2u(float lo, float hi) {
    __half2 h = __floats2half2_rn(lo, hi);
    return *(unsigned*)&h;
}

// smem words (3-deep ring): ws[tap][ci2][136]=9792, xs[row][ci2][136] (4 rows)=4352
#define WS_W 9792
#define XS_W 4352
#define BUF_W (WS_W + XS_W)
#define SMEM_BYTES (3 * BUF_W * 4)
// scan buffer (conv3 epilogue): 256 rows x pitch 132 fp32 = 135168 B <= SMEM_BYTES

// ---------------------------------------------------------------------------
// fp16 mma.sync implicit-GEMM 3x3 conv + BN (+ReLU), 3-deep cp.async ring.
// Block=256, tile M=128co x 256px (2 rows x 128w), K streamed 16ci/chunk.
// OUT=0: emit half2 pair tensor. OUT=1: fused reverse-cummax over W (LeftPool),
//        emit fp32 NCHW directly.
// gridDim.z=2 selects (w0,p0,o0) vs (w1,p1,o1) per block (merged conv1+conv2).
// ---------------------------------------------------------------------------
template <int NCC, bool RELU, int OUT>
__global__ __launch_bounds__(256, 1)
void conv_h(const unsigned* __restrict__ xh,
            const unsigned* __restrict__ w0p, const unsigned* __restrict__ w1p,
            BNP p0, BNP p1,
            unsigned* __restrict__ o0, unsigned* __restrict__ o1)
{
    extern __shared__ unsigned sm[];

    const int tid  = threadIdx.x;
    const int b    = blockIdx.y;
    const int h0   = blockIdx.x * 2;
    const int z    = blockIdx.z;

    const unsigned* wh = z ? w1p : w0p;
    const BNP       pp = z ? p1 : p0;
    unsigned*     outv = z ? o1 : o0;

    const int warp = tid >> 5;
    const int lane = tid & 31;
    const int g    = lane >> 2;
    const int tig  = lane & 3;

    const int mwarp  = warp & 1;
    const int nwarp  = warp >> 1;
    const int rloc   = nwarp >> 1;
    const int wn0    = (nwarp & 1) * 64;
    const int cobase = mwarp * 64;

    // static-zero halo cols (3 <- w=-1, 132 <- w=128): 3 bufs x 4 rows x 8 ci2 x 2 cols
    if (tid < 192) {
        int buf = tid >> 6, rem = tid & 63;
        int colsel = rem & 1, ci2 = (rem >> 1) & 7, row = (rem >> 4) & 3;
        sm[buf * BUF_W + WS_W + row * 1088 + ci2 * 136 + (colsel ? 132 : 3)] = 0u;
    }

    float acc[4][8][4];
#pragma unroll
    for (int mt = 0; mt < 4; mt++)
#pragma unroll
        for (int nt = 0; nt < 8; nt++)
#pragma unroll
            for (int i = 0; i < 4; i++) acc[mt][nt][i] = 0.f;

    auto stage = [&](int c) {
        unsigned* ws = sm + (c % 3) * BUF_W;
        unsigned* xs = ws + WS_W;
#pragma unroll
        for (int k = 0; k < 9; k++) {
            int fi = tid + (k << 8);
            int tap = fi >> 8, rem = fi & 255, ci2 = rem >> 5, cg = rem & 31;
            cpa16(ws + (tap * 8 + ci2) * 136 + cg * 4,
                  wh + (size_t)(c * 9 + tap) * 1024 + ci2 * 128 + cg * 4, true);
        }
#pragma unroll
        for (int k = 0; k < 4; k++) {
            int fi = tid + (k << 8);
            int row = fi >> 8, rem = fi & 255, ci2 = rem >> 5, wg = rem & 31;
            int gh = h0 - 1 + row;
            bool ok = (gh >= 0) && (gh < H_);
            cpa16(xs + row * 1088 + ci2 * 136 + 4 + wg * 4,
                  xh + ((size_t)((b * NCC + c) * 8 + ci2) * H_ + (ok ? gh : 0)) * W_ + wg * 4,
                  ok);
        }
    };

    stage(0); CPCOMMIT();
    stage(1); CPCOMMIT();

    for (int c = 0; c < NCC; c++) {
        if (c + 1 < NCC) { CPWAIT(1); } else { CPWAIT(0); }
        __syncthreads();   // stage(c) visible; all warps done with compute(c-1)
        if (c + 2 < NCC) { stage(c + 2); CPCOMMIT(); }   // buf (c+2)%3 == (c-1)%3, free

        const unsigned* ws = sm + (c % 3) * BUF_W;
        const unsigned* xs = ws + WS_W;

#pragma unroll
        for (int dh = 0; dh < 3; dh++)
#pragma unroll
            for (int dw = 0; dw < 3; dw++) {
                const int tap = dh * 3 + dw;
                const unsigned* wr0 = ws + (tap * 8 + tig) * 136;
                const unsigned* wr1 = ws + (tap * 8 + tig + 4) * 136;
                unsigned a[4][4];
#pragma unroll
                for (int mt = 0; mt < 4; mt++) {
                    int cb = cobase + mt * 16 + g;
                    a[mt][0] = wr0[cb];
                    a[mt][1] = wr0[cb + 8];
                    a[mt][2] = wr1[cb];
                    a[mt][3] = wr1[cb + 8];
                }
                const unsigned* p0 = xs + (rloc + dh) * 1088 + tig * 136 + wn0 + g + dw + 3;
                const unsigned* p1 = p0 + 4 * 136;
#pragma unroll
                for (int nt = 0; nt < 8; nt++) {
                    unsigned b0 = p0[nt * 8];
                    unsigned b1 = p1[nt * 8];
#pragma unroll
                    for (int mt = 0; mt < 4; mt++)
                        mma_f16(acc[mt][nt], a[mt], b0, b1);
                }
            }
    }

    // ---- epilogue: BN (+ReLU) ----
    const int h = h0 + rloc;
    if (OUT == 0) {
#pragma unroll
        for (int mt = 0; mt < 4; mt++) {
            int ca = cobase + mt * 16 + g;
            int cb2 = ca + 8;
            float inva = pp.g[ca]  * rsqrtf(pp.v[ca]  + 1e-5f);
            float bia  = pp.b[ca]  - pp.m[ca]  * inva;
            float invb = pp.g[cb2] * rsqrtf(pp.v[cb2] + 1e-5f);
            float bib  = pp.b[cb2] - pp.m[cb2] * invb;
            int j = (mwarp * 4 + mt) * 8 + g;   // pair row
            unsigned* rp = outv + ((size_t)(b * 64 + j) * H_ + h) * W_;
#pragma unroll
            for (int nt = 0; nt < 8; nt++) {
                int w0 = wn0 + nt * 8 + 2 * tig;
                float v0 = acc[mt][nt][0] * inva + bia;
                float v1 = acc[mt][nt][1] * inva + bia;
                float v2 = acc[mt][nt][2] * invb + bib;
                float v3 = acc[mt][nt][3] * invb + bib;
                if (RELU) { v0=fmaxf(v0,0.f); v1=fmaxf(v1,0.f); v2=fmaxf(v2,0.f); v3=fmaxf(v3,0.f); }
                uint2 q; q.x = h2u(v0, v2); q.y = h2u(v1, v3);
                *(uint2*)(rp + w0) = q;
            }
        }
    } else {
        // ---- fused LeftPool: BN -> smem -> reverse cummax over W -> fp32 NCHW ----
        float* sc = (float*)sm;               // [256 rows (co*2+r)][pitch 132]
        __syncthreads();                      // mainloop smem reads complete everywhere
#pragma unroll
        for (int mt = 0; mt < 4; mt++) {
            int ca = cobase + mt * 16 + g;
            int cb2 = ca + 8;
            float inva = pp.g[ca]  * rsqrtf(pp.v[ca]  + 1e-5f);
            float bia  = pp.b[ca]  - pp.m[ca]  * inva;
            float invb = pp.g[cb2] * rsqrtf(pp.v[cb2] + 1e-5f);
            float bib  = pp.b[cb2] - pp.m[cb2] * invb;
            float* r0 = sc + (ca * 2 + rloc) * 132;
            float* r1 = sc + (cb2 * 2 + rloc) * 132;
#pragma unroll
            for (int nt = 0; nt < 8; nt++) {
                int w0 = wn0 + nt * 8 + 2 * tig;
                *(float2*)(r0 + w0) = make_float2(acc[mt][nt][0] * inva + bia,
                                                  acc[mt][nt][1] * inva + bia);
                *(float2*)(r1 + w0) = make_float2(acc[mt][nt][2] * invb + bib,
                                                  acc[mt][nt][3] * invb + bib);
            }
        }
        __syncthreads();
        // per-thread serial reverse max-scan of one (co,r) row
        {
            float* rw = sc + tid * 132;
            float run = -INFINITY;
#pragma unroll 4
            for (int w = W_ - 1; w >= 0; w--) {
                run = fmaxf(run, rw[w]);
                rw[w] = run;
            }
        }
        __syncthreads();
        // coalesced float4 store to fp32 NCHW output
        float* outf = (float*)outv;
#pragma unroll
        for (int k = 0; k < 32; k++) {
            int idx4 = tid + (k << 8);        // 8192 float4s
            int co = idx4 >> 6;
            int r  = (idx4 >> 5) & 1;
            int w4 = idx4 & 31;
            float4 q = *(float4*)(sc + (co * 2 + r) * 132 + w4 * 4);
            ((float4*)(outf + (((size_t)b * COUT + co) * H_ + h0 + r) * W_))[w4] = q;
        }
    }
}

// ---------------------------------------------------------------------------
// Merged prep: xpose (2-wide) + all three weight packs in ONE kernel.
// Keeps the graph at 4 kernels/iteration so ncu -s 5 captures conv_h.
// ---------------------------------------------------------------------------
#define XP_BLKS 65536          // (B*128*H*W/2) / 256
#define WP1_BLKS 576           // (128*9*128)/256
#define WP3_BLKS 288           // (64*9*128)/256

__device__ __forceinline__ void wpack_body(int idx, int CIN, bool PAIR8,
                                           const float* __restrict__ w,
                                           unsigned* __restrict__ wo)
{
    int co = idx & 127;
    int tap = (idx >> 7) % 9;
    int jg = idx / (9 * 128);
    int ca, cbb;
    if (PAIR8) { ca = (jg >> 3) * 16 + (jg & 7); cbb = ca + 8; }
    else       { ca = 2 * jg;                    cbb = ca + 1; }
    float wa = w[((size_t)co * CIN + ca)  * 9 + tap];
    float wb = w[((size_t)co * CIN + cbb) * 9 + tap];
    wo[((size_t)((jg >> 3) * 9 + tap)) * 1024 + (jg & 7) * 128 + co] = h2u(wa, wb);
}

__global__ void prep_all(const float* __restrict__ x, unsigned* __restrict__ xh,
                         const float* __restrict__ w_up,   unsigned* __restrict__ whu,
                         const float* __restrict__ w_down, unsigned* __restrict__ whd,
                         const float* __restrict__ w_p,    unsigned* __restrict__ whp)
{
    int blk = blockIdx.x;
    if (blk < XP_BLKS) {
        // xpose, 2 half2 per thread
        size_t e = (size_t)blk * 256 + threadIdx.x;   // pair-of-w index
        int w2  = (int)(e & 63);
        int h   = (int)((e >> 6) & 127);
        int ci2 = (int)((e >> 13) & 127);
        int b   = (int)(e >> 20);
        const float* p0 = x + (((size_t)b * CIN1 + 2 * ci2)     * H_ + h) * W_ + 2 * w2;
        const float* p1 = x + (((size_t)b * CIN1 + 2 * ci2 + 1) * H_ + h) * W_ + 2 * w2;
        float2 a = *(const float2*)p0;
        float2 c = *(const float2*)p1;
        uint2 q; q.x = h2u(a.x, c.x); q.y = h2u(a.y, c.y);
        *(uint2*)(xh + (((size_t)b * 128 + ci2) * H_ + h) * W_ + 2 * w2) = q;
    } else if (blk < XP_BLKS + WP1_BLKS) {
        int idx = (blk - XP_BLKS) * 256 + threadIdx.x;
        wpack_body(idx, CIN1, false, w_up, whu);
    } else if (blk < XP_BLKS + 2 * WP1_BLKS) {
        int idx = (blk - XP_BLKS - WP1_BLKS) * 256 + threadIdx.x;
        wpack_body(idx, CIN1, false, w_down, whd);
    } else {
        int idx = (blk - XP_BLKS - 2 * WP1_BLKS) * 256 + threadIdx.x;
        wpack_body(idx, COUT, true, w_p, whp);
    }
}

// ---------------------------------------------------------------------------
// TopPool (reverse cummax over H) + add on half2 pair tensors.
// ---------------------------------------------------------------------------
__global__ void tpool_h(const unsigned* __restrict__ up, const unsigned* __restrict__ dn,
                        unsigned* __restrict__ mg)
{
    int idx = blockIdx.x * 256 + threadIdx.x;   // B*64*W
    int w = idx & 127;
    int bj = idx >> 7;
    size_t base = (size_t)bj * H_ * W_ + w;
    unsigned ru = 0xFC00FC00u;                  // half2(-inf,-inf)
    __half2 run = *(__half2*)&ru;
#pragma unroll 4
    for (int h = H_ - 1; h >= 0; h--) {
        size_t o = base + (size_t)h * W_;
        __half2 u = *(__half2*)&up[o];
        __half2 d = *(__half2*)&dn[o];
        run = __hmax2(run, u);
        __half2 m = __hadd2(run, d);
        mg[o] = *(unsigned*)&m;
    }
}

// ---------------------------------------------------------------------------
extern "C" void kernel_launch(void* const* d_in, const int* in_sizes, int n_in,
                              void* d_out, int out_size)
{
    const float* x      = (const float*)d_in[0];
    const float* w_up   = (const float*)d_in[1];
    const float* up_g   = (const float*)d_in[2];
    const float* up_b   = (const float*)d_in[3];
    const float* up_m   = (const float*)d_in[4];
    const float* up_v   = (const float*)d_in[5];
    const float* w_down = (const float*)d_in[6];
    const float* dn_g   = (const float*)d_in[7];
    const float* dn_b   = (const float*)d_in[8];
    const float* dn_m   = (const float*)d_in[9];
    const float* dn_v   = (const float*)d_in[10];
    const float* w_p    = (const float*)d_in[11];
    const float* p_g    = (const float*)d_in[12];
    const float* p_b    = (const float*)d_in[13];
    const float* p_m    = (const float*)d_in[14];
    const float* p_v    = (const float*)d_in[15];
    float* outp = (float*)d_out;

    unsigned *xh, *uph, *dnh, *whu, *whd, *whp;
    cudaGetSymbolAddress((void**)&xh,  g_xh);
    cudaGetSymbolAddress((void**)&uph, g_uph);
    cudaGetSymbolAddress((void**)&dnh, g_dnh);
    cudaGetSymbolAddress((void**)&whu, g_whu);
    cudaGetSymbolAddress((void**)&whd, g_whd);
    cudaGetSymbolAddress((void**)&whp, g_whp);

    cudaFuncSetAttribute(conv_h<16, true,  0>, cudaFuncAttributeMaxDynamicSharedMemorySize, SMEM_BYTES);
    cudaFuncSetAttribute(conv_h< 8, false, 1>, cudaFuncAttributeMaxDynamicSharedMemorySize, SMEM_BYTES);

    // prep (single kernel: xpose + all weight packs)
    prep_all<<<XP_BLKS + 2 * WP1_BLKS + WP3_BLKS, 256>>>(
        x, xh, w_up, whu, w_down, whd, w_p, whp);

    BNP pup = { up_g, up_b, up_m, up_v };
    BNP pdn = { dn_g, dn_b, dn_m, dn_v };
    BNP ppp = { p_g,  p_b,  p_m,  p_v  };

    // conv1 + conv2 merged (z selects weight/BN/output set)
    dim3 g12(H_ / 2, B_, 2);
    conv_h<16, true, 0><<<g12, 256, SMEM_BYTES>>>(xh, whu, whd, pup, pdn, uph, dnh);
    // merge = toppool(up) + down
    tpool_h<<<(B_ * 64 * W_) / 256, 256>>>(uph, dnh, dnh);
    // conv3 + BN + fused LeftPool -> fp32 output
    dim3 g3(H_ / 2, B_, 1);
    conv_h<8, false, 1><<<g3, 256, SMEM_BYTES>>>(dnh, whp, whp, ppp, ppp,
                                                 (unsigned*)outp, (unsigned*)outp);
}